// round 3
// baseline (speedup 1.0000x reference)
#include <cuda_runtime.h>
#include <math_constants.h>

// CustomSoftmaxExperts: rows of 64 fp32 logits.
// out = softmax(x) masked to entries that are >= 5th-largest softmax value
//       AND >= 0.2, else 0.
//
// One warp per row, 2 elements per lane (float2, fully coalesced).
// 5th-largest softmax value = exp(x5 - max)/sum (softmax is monotone),
// computed with the SAME arithmetic as the per-element softmax so the
// >= comparison is exact at the kth element.

#define THRESHOLD 0.2f

__global__ __launch_bounds__(256, 8)
void softmax_experts_kernel(const float* __restrict__ in,
                            float* __restrict__ out,
                            int nrows)
{
    const int gwarp = (blockIdx.x * blockDim.x + threadIdx.x) >> 5;
    const int lane  = threadIdx.x & 31;
    if (gwarp >= nrows) return;

    const unsigned FULL = 0xFFFFFFFFu;

    // Coalesced 64-bit load: lane l gets elements [2l, 2l+1] of the row.
    const float2* ip = reinterpret_cast<const float2*>(in) + (size_t)gwarp * 32 + lane;
    float2 v = *ip;

    // ---- row max ----
    float m = fmaxf(v.x, v.y);
    #pragma unroll
    for (int o = 16; o; o >>= 1)
        m = fmaxf(m, __shfl_xor_sync(FULL, m, o));

    // ---- exp + row sum ----
    float e0 = __expf(v.x - m);
    float e1 = __expf(v.y - m);
    float s  = e0 + e1;
    #pragma unroll
    for (int o = 16; o; o >>= 1)
        s += __shfl_xor_sync(FULL, s, o);
    float inv_sum = __frcp_rn(s);

    // ---- 5th-largest raw value via 5 rounds of warp-max + single removal ----
    float a0 = v.x, a1 = v.y;
    float kth = -CUDART_INF_F;
    #pragma unroll
    for (int i = 0; i < 5; i++) {
        float mm = fmaxf(a0, a1);
        float r = mm;
        #pragma unroll
        for (int o = 16; o; o >>= 1)
            r = fmaxf(r, __shfl_xor_sync(FULL, r, o));
        kth = r;
        // remove exactly one occurrence of r (lowest lane holding it)
        unsigned ball = __ballot_sync(FULL, mm == r);
        if (lane == (__ffs(ball) - 1)) {
            if (a0 == r) a0 = -CUDART_INF_F;
            else         a1 = -CUDART_INF_F;
        }
    }

    // kth softmax value, computed with identical arithmetic as per-element s
    float sk = __expf(kth - m) * inv_sum;

    float s0 = e0 * inv_sum;
    float s1 = e1 * inv_sum;

    float2 o2;
    o2.x = (s0 >= sk && s0 >= THRESHOLD) ? s0 : 0.0f;
    o2.y = (s1 >= sk && s1 >= THRESHOLD) ? s1 : 0.0f;

    float2* op = reinterpret_cast<float2*>(out) + (size_t)gwarp * 32 + lane;
    *op = o2;
}

extern "C" void kernel_launch(void* const* d_in, const int* in_sizes, int n_in,
                              void* d_out, int out_size)
{
    const float* in  = (const float*)d_in[0];
    float*       out = (float*)d_out;
    int nrows = in_sizes[0] / 64;   // 32 * 8192 = 262144

    const int threads = 256;                  // 8 warps -> 8 rows per block
    int blocks = (nrows * 32 + threads - 1) / threads;
    softmax_experts_kernel<<<blocks, threads>>>(in, out, nrows);
}

// round 5
// speedup vs baseline: 2.1007x; 2.1007x over previous
#include <cuda_runtime.h>

// CustomSoftmaxExperts, simplified.
//
// Reference mask: (softmax >= kth_of_top5) & (softmax >= 0.2).
// Since softmax sums to 1, any value >= 0.2 can have at most 4 values
// strictly above it (else sum > 1.2), so it is automatically in the top 5
// and >= kth. The top-k condition is vacuous: mask == (softmax >= 0.2).
//
// Layout: 16 lanes per row, 4 fp32 per lane (float4 -> LDG.128/STG.128).
// One warp processes 2 rows; reductions are 4 xor-shuffles within the
// 16-lane half-group (offsets 8,4,2,1 never cross the group boundary).

#define THRESHOLD 0.2f

__global__ __launch_bounds__(256, 8)
void softmax_thresh_kernel(const float4* __restrict__ in,
                           float4* __restrict__ out,
                           int nrows)
{
    // global half-warp index == row index
    const int tid  = blockIdx.x * blockDim.x + threadIdx.x;
    const int row  = tid >> 4;          // 16 lanes per row
    const int l16  = threadIdx.x & 15;  // lane within row group
    if (row >= nrows) return;

    const unsigned FULL = 0xFFFFFFFFu;

    // Row has 64 floats = 16 float4s; lane l16 takes the l16-th float4.
    const size_t base = (size_t)row * 16 + l16;
    float4 v = in[base];

    // ---- row max (tree within 16-lane group) ----
    float m = fmaxf(fmaxf(v.x, v.y), fmaxf(v.z, v.w));
    #pragma unroll
    for (int o = 8; o; o >>= 1)
        m = fmaxf(m, __shfl_xor_sync(FULL, m, o));

    // ---- exp + row sum ----
    float e0 = __expf(v.x - m);
    float e1 = __expf(v.y - m);
    float e2 = __expf(v.z - m);
    float e3 = __expf(v.w - m);
    float s  = (e0 + e1) + (e2 + e3);
    #pragma unroll
    for (int o = 8; o; o >>= 1)
        s += __shfl_xor_sync(FULL, s, o);
    float inv = __frcp_rn(s);

    // ---- softmax + threshold mask ----
    float s0 = e0 * inv;
    float s1 = e1 * inv;
    float s2 = e2 * inv;
    float s3 = e3 * inv;

    float4 o4;
    o4.x = (s0 >= THRESHOLD) ? s0 : 0.0f;
    o4.y = (s1 >= THRESHOLD) ? s1 : 0.0f;
    o4.z = (s2 >= THRESHOLD) ? s2 : 0.0f;
    o4.w = (s3 >= THRESHOLD) ? s3 : 0.0f;

    out[base] = o4;
}

extern "C" void kernel_launch(void* const* d_in, const int* in_sizes, int n_in,
                              void* d_out, int out_size)
{
    const float4* in  = (const float4*)d_in[0];
    float4*       out = (float4*)d_out;
    int nrows = in_sizes[0] / 64;      // 32 * 8192 = 262144

    const int threads = 256;           // 16 rows per block
    int blocks = (nrows * 16 + threads - 1) / threads;
    softmax_thresh_kernel<<<blocks, threads>>>(in, out, nrows);
}

// round 6
// speedup vs baseline: 2.5411x; 1.2096x over previous
#include <cuda_runtime.h>

// CustomSoftmaxExperts, threshold-only form (top-5 condition proven vacuous:
// softmax >= 0.2 implies membership in top 5 since values sum to 1).
//
// Layout: 4 lanes per row, 16 fp32 (4x float4) per thread.
//  - 4 independent LDG.128 per thread -> MLP=4 per thread.
//  - reductions need only 2 xor-shuffles (offsets 2,1) within the 4-lane group.
//  - 16 independent __expf per thread give MUFU ILP during shuffle waits.

#define THRESHOLD 0.2f

__global__ __launch_bounds__(256)
void softmax_thresh_kernel(const float4* __restrict__ in,
                           float4* __restrict__ out,
                           int nrows)
{
    const int tid = blockIdx.x * blockDim.x + threadIdx.x;
    const int row = tid >> 2;           // 4 lanes per row
    const int l4  = threadIdx.x & 3;    // lane within row group
    if (row >= nrows) return;

    const unsigned FULL = 0xFFFFFFFFu;

    // Row = 64 floats = 16 float4s. Lane l4 takes float4s {l4, l4+4, l4+8, l4+12}.
    // Across the warp each of the 4 loads is a contiguous 512B segment.
    const size_t base = (size_t)row * 16 + l4;
    float4 v0 = in[base];
    float4 v1 = in[base + 4];
    float4 v2 = in[base + 8];
    float4 v3 = in[base + 12];

    // ---- local max over 16 elems (ILP tree) ----
    float m01 = fmaxf(fmaxf(v0.x, v0.y), fmaxf(v0.z, v0.w));
    float m23 = fmaxf(fmaxf(v1.x, v1.y), fmaxf(v1.z, v1.w));
    float m45 = fmaxf(fmaxf(v2.x, v2.y), fmaxf(v2.z, v2.w));
    float m67 = fmaxf(fmaxf(v3.x, v3.y), fmaxf(v3.z, v3.w));
    float m = fmaxf(fmaxf(m01, m23), fmaxf(m45, m67));

    // ---- row max: 2 shuffles within the 4-lane group ----
    m = fmaxf(m, __shfl_xor_sync(FULL, m, 2));
    m = fmaxf(m, __shfl_xor_sync(FULL, m, 1));

    // ---- exp (16 independent MUFU ops) + local sum ----
    float e0x = __expf(v0.x - m), e0y = __expf(v0.y - m);
    float e0z = __expf(v0.z - m), e0w = __expf(v0.w - m);
    float e1x = __expf(v1.x - m), e1y = __expf(v1.y - m);
    float e1z = __expf(v1.z - m), e1w = __expf(v1.w - m);
    float e2x = __expf(v2.x - m), e2y = __expf(v2.y - m);
    float e2z = __expf(v2.z - m), e2w = __expf(v2.w - m);
    float e3x = __expf(v3.x - m), e3y = __expf(v3.y - m);
    float e3z = __expf(v3.z - m), e3w = __expf(v3.w - m);

    float s = ((e0x + e0y) + (e0z + e0w))
            + ((e1x + e1y) + (e1z + e1w))
            + ((e2x + e2y) + (e2z + e2w))
            + ((e3x + e3y) + (e3z + e3w));

    // ---- row sum: 2 shuffles ----
    s += __shfl_xor_sync(FULL, s, 2);
    s += __shfl_xor_sync(FULL, s, 1);
    float inv = __frcp_rn(s);

    // ---- softmax + threshold, 4 STG.128 ----
    float4 o;
    float t;
    t = e0x * inv; o.x = (t >= THRESHOLD) ? t : 0.0f;
    t = e0y * inv; o.y = (t >= THRESHOLD) ? t : 0.0f;
    t = e0z * inv; o.z = (t >= THRESHOLD) ? t : 0.0f;
    t = e0w * inv; o.w = (t >= THRESHOLD) ? t : 0.0f;
    out[base] = o;

    t = e1x * inv; o.x = (t >= THRESHOLD) ? t : 0.0f;
    t = e1y * inv; o.y = (t >= THRESHOLD) ? t : 0.0f;
    t = e1z * inv; o.z = (t >= THRESHOLD) ? t : 0.0f;
    t = e1w * inv; o.w = (t >= THRESHOLD) ? t : 0.0f;
    out[base + 4] = o;

    t = e2x * inv; o.x = (t >= THRESHOLD) ? t : 0.0f;
    t = e2y * inv; o.y = (t >= THRESHOLD) ? t : 0.0f;
    t = e2z * inv; o.z = (t >= THRESHOLD) ? t : 0.0f;
    t = e2w * inv; o.w = (t >= THRESHOLD) ? t : 0.0f;
    out[base + 8] = o;

    t = e3x * inv; o.x = (t >= THRESHOLD) ? t : 0.0f;
    t = e3y * inv; o.y = (t >= THRESHOLD) ? t : 0.0f;
    t = e3z * inv; o.z = (t >= THRESHOLD) ? t : 0.0f;
    t = e3w * inv; o.w = (t >= THRESHOLD) ? t : 0.0f;
    out[base + 12] = o;
}

extern "C" void kernel_launch(void* const* d_in, const int* in_sizes, int n_in,
                              void* d_out, int out_size)
{
    const float4* in  = (const float4*)d_in[0];
    float4*       out = (float4*)d_out;
    int nrows = in_sizes[0] / 64;      // 262144

    const int threads = 256;           // 64 rows per block
    int blocks = (nrows * 4 + threads - 1) / threads;
    softmax_thresh_kernel<<<blocks, threads>>>(in, out, nrows);
}